// round 15
// baseline (speedup 1.0000x reference)
#include <cuda_runtime.h>
#include <cuda_bf16.h>
#include <cstdint>

#define T_ 4
#define B_ 8
#define C_ 512
#define D_ 768
#define H_ 8
#define HD_ 96
#define MKV_ 192
#define NCAT_ 1152            // 768 (q) + 192 (k) + 192 (v)
#define BC_ 4096              // B*C
#define M_ 16384              // T*B*C
#define BCD_ 3145728          // B*C*D

// ---------------- scratch (device globals: no allocation allowed) ----------
__device__ __nv_bfloat16 g_xs[M_ * D_];        // proj_lif spikes (exact 0/1)
__device__ __nv_bfloat16 g_Whi[NCAT_ * D_];    // concat [q_w; k_w; v_w] hi
__device__ __nv_bfloat16 g_Wlo[NCAT_ * D_];    // lo residual
__device__ __nv_bfloat16 g_WOhi[D_ * D_];
__device__ __nv_bfloat16 g_WOlo[D_ * D_];
__device__ __nv_bfloat16 g_sp[M_ * NCAT_];     // q/k/v spikes (bf16 0/1, exact)
__device__ __nv_bfloat16 g_ahi[M_ * D_];       // attention output hi
__device__ __nv_bfloat16 g_alo[M_ * D_];       // attention output lo

// ---------------- helpers ----------------
__device__ __forceinline__ uint32_t smem_u32(const void* p) {
    uint32_t a;
    asm("{ .reg .u64 t; cvta.to.shared.u64 t, %1; cvt.u32.u64 %0, t; }" : "=r"(a) : "l"(p));
    return a;
}
__device__ __forceinline__ void mma_bf16(float* c, const uint32_t* a, const uint32_t* b) {
    asm volatile(
        "mma.sync.aligned.m16n8k16.row.col.f32.bf16.bf16.f32 "
        "{%0,%1,%2,%3},{%4,%5,%6,%7},{%8,%9},{%0,%1,%2,%3};\n"
        : "+f"(c[0]), "+f"(c[1]), "+f"(c[2]), "+f"(c[3])
        : "r"(a[0]), "r"(a[1]), "r"(a[2]), "r"(a[3]), "r"(b[0]), "r"(b[1]));
}
__device__ __forceinline__ void ldsm_x4(uint32_t* r, uint32_t addr) {
    asm volatile("ldmatrix.sync.aligned.m8n8.x4.shared.b16 {%0,%1,%2,%3}, [%4];"
        : "=r"(r[0]), "=r"(r[1]), "=r"(r[2]), "=r"(r[3]) : "r"(addr));
}
__device__ __forceinline__ void ldsm_x4_t(uint32_t* r, uint32_t addr) {
    asm volatile("ldmatrix.sync.aligned.m8n8.x4.trans.shared.b16 {%0,%1,%2,%3}, [%4];"
        : "=r"(r[0]), "=r"(r[1]), "=r"(r[2]), "=r"(r[3]) : "r"(addr));
}
__device__ __forceinline__ uint32_t pack_bf16x2(float lo, float hi) {
    uint32_t r;
    asm("cvt.rn.bf16x2.f32 %0, %1, %2;" : "=r"(r) : "f"(hi), "f"(lo));
    return r;
}
__device__ __forceinline__ void cpa16(uint32_t dst, const void* src) {
    asm volatile("cp.async.ca.shared.global [%0], [%1], 16;" :: "r"(dst), "l"(src));
}
#define CP_COMMIT()  asm volatile("cp.async.commit_group;" ::: "memory")
#define CP_WAIT(n)   asm volatile("cp.async.wait_group %0;" :: "n"(n) : "memory")

// ---------------- kernel 1: split weights into bf16 hi/lo ----------------
__global__ void pack_w_k(const float* __restrict__ qw, const float* __restrict__ kw,
                         const float* __restrict__ vw, const float* __restrict__ wow) {
    int i = blockIdx.x * 256 + threadIdx.x;
    if (i < NCAT_ * D_) {
        int n = i / D_, k = i - n * D_;
        float w;
        if (n < D_)            w = qw[i];
        else if (n < D_ + MKV_) w = kw[(n - D_) * D_ + k];
        else                    w = vw[(n - D_ - MKV_) * D_ + k];
        __nv_bfloat16 hi = __float2bfloat16(w);
        g_Whi[i] = hi;
        g_Wlo[i] = __float2bfloat16(w - __bfloat162float(hi));
    }
    if (i < D_ * D_) {
        float w = wow[i];
        __nv_bfloat16 hi = __float2bfloat16(w);
        g_WOhi[i] = hi;
        g_WOlo[i] = __float2bfloat16(w - __bfloat162float(hi));
    }
}

// ---------------- kernel 2: LIF on x -> xs spikes (bf16 exact) -------------
__global__ void lif_x_k(const float* __restrict__ x) {
    int i = blockIdx.x * 256 + threadIdx.x;
    if (i >= BCD_) return;
    float v = 0.f;
#pragma unroll
    for (int t = 0; t < T_; t++) {
        v = v * 0.5f + x[t * BCD_ + i];
        bool s = (v >= 1.0f);
        g_xs[t * BCD_ + i] = __float2bfloat16(s ? 1.f : 0.f);
        if (s) v = 0.f;
    }
}

// ====== kernel 3: FUSED projection GEMM + LIF (membrane-in-accumulator) ====
#define PSTR 40                 // smem row stride, bf16 units
#define PSTRB 80                // ... bytes
#define PTILE (128 * PSTR)      // tile bf16 units
#define PTILEB (128 * PSTRB)    // tile bytes (10240)
#define PSTGB (3 * PTILEB)      // 30720
#define NCH 24                  // K=768 / 32
__global__ void __launch_bounds__(256, 2)
gemm_proj_fused() {
    extern __shared__ __nv_bfloat16 smp[];
    uint32_t sbase = smem_u32(smp);
    int tid = threadIdx.x;
    int lane = tid & 31, warp = tid >> 5;
    int gid = lane >> 2, tig = lane & 3;
    int wm = (warp >> 2) * 64, wn = (warp & 3) * 32;
    int m0 = blockIdx.y * 128;            // within one t-slice (BC rows)
    int n0 = blockIdx.x * 128;

    uint32_t a_off = (wm + (lane & 15)) * PSTRB + (lane >> 4) * 16;
    uint32_t b_off = (wn + ((lane >> 4) << 3) + (lane & 7)) * PSTRB + ((lane >> 3) & 1) * 16;

    float acc[4][4][4];                   // doubles as LIF membrane (x0.5)
#pragma unroll
    for (int a = 0; a < 4; a++)
#pragma unroll
        for (int b = 0; b < 4; b++)
#pragma unroll
            for (int c = 0; c < 4; c++) acc[a][b][c] = 0.f;

    int r0 = tid >> 2, c4b = (tid & 3) * 16;

    for (int t = 0; t < T_; t++) {
        size_t mrow = (size_t)(t * BC_ + m0);
#pragma unroll
        for (int it = 0; it < 2; it++) {
            int rr = r0 + it * 64;
            cpa16(sbase + rr * PSTRB + c4b,
                  (const char*)(g_xs + (mrow + rr) * D_) + c4b);
            cpa16(sbase + PTILEB + rr * PSTRB + c4b,
                  (const char*)(g_Whi + (size_t)(n0 + rr) * D_) + c4b);
            cpa16(sbase + 2 * PTILEB + rr * PSTRB + c4b,
                  (const char*)(g_Wlo + (size_t)(n0 + rr) * D_) + c4b);
        }
        CP_COMMIT();

        for (int c = 0; c < NCH; c++) {
            if (c + 1 < NCH) {
                uint32_t st = ((c + 1) & 1) * PSTGB;
                int kb = (c + 1) * 64;
#pragma unroll
                for (int it = 0; it < 2; it++) {
                    int rr = r0 + it * 64;
                    cpa16(sbase + st + rr * PSTRB + c4b,
                          (const char*)(g_xs + (mrow + rr) * D_) + kb + c4b);
                    cpa16(sbase + st + PTILEB + rr * PSTRB + c4b,
                          (const char*)(g_Whi + (size_t)(n0 + rr) * D_) + kb + c4b);
                    cpa16(sbase + st + 2 * PTILEB + rr * PSTRB + c4b,
                          (const char*)(g_Wlo + (size_t)(n0 + rr) * D_) + kb + c4b);
                }
                CP_COMMIT();
                CP_WAIT(1);
            } else {
                CP_WAIT(0);
            }
            __syncthreads();
            uint32_t off = (c & 1) * PSTGB;
            uint32_t a_base = sbase + off + a_off;
            uint32_t bh_base = sbase + off + PTILEB + b_off;
            uint32_t bl_base = sbase + off + 2 * PTILEB + b_off;
#pragma unroll
            for (int kk = 0; kk < 2; kk++) {
                uint32_t af[4][4], bh[2][4], bl[2][4];
#pragma unroll
                for (int mt = 0; mt < 4; mt++)
                    ldsm_x4(af[mt], a_base + mt * (16 * PSTRB) + kk * 32);
#pragma unroll
                for (int j = 0; j < 2; j++) {
                    ldsm_x4(bh[j], bh_base + j * (16 * PSTRB) + kk * 32);
                    ldsm_x4(bl[j], bl_base + j * (16 * PSTRB) + kk * 32);
                }
#pragma unroll
                for (int nt = 0; nt < 4; nt++) {
                    const uint32_t* bhp = &bh[nt >> 1][(nt & 1) * 2];
                    const uint32_t* blp = &bl[nt >> 1][(nt & 1) * 2];
#pragma unroll
                    for (int mt = 0; mt < 4; mt++) {
                        mma_bf16(acc[mt][nt], af[mt], bhp);
                        mma_bf16(acc[mt][nt], af[mt], blp);
                    }
                }
            }
            __syncthreads();
        }

        // LIF epilogue for this t: acc == v_t. Emit spikes, set acc = 0.5*v'.
#pragma unroll
        for (int mt = 0; mt < 4; mt++)
#pragma unroll
            for (int nt = 0; nt < 4; nt++) {
                int col = n0 + wn + nt * 8 + tig * 2;
                uint32_t w[2];
#pragma unroll
                for (int half = 0; half < 2; half++) {
                    uint32_t pk = 0;
#pragma unroll
                    for (int j = 0; j < 2; j++) {
                        int i = half * 2 + j;
                        float v = acc[mt][nt][i];
                        bool sp = (v >= 1.0f);
                        if (sp) pk |= 0x3F80u << (j * 16);
                        acc[mt][nt][i] = sp ? 0.f : v * 0.5f;
                    }
                    w[half] = pk;
                }
                size_t r = mrow + wm + mt * 16 + gid;
                *(uint32_t*)(g_sp + r * NCAT_ + col) = w[0];
                *(uint32_t*)(g_sp + (r + 8) * NCAT_ + col) = w[1];
            }
    }
}

// ====== kernel 4: attention, key-split warps, 2 CTAs/SM ====================
// CTA: 64 q-rows; 8 warps = 4 row-groups x 2 key-halves (64 keys each).
// Register-resident P, single-buffered K/V (co-resident CTA overlaps), final
// cross-half acc2 reduction through smem (aliases dead K buffer).
// smem bytes: Q[64x208]=13312 | K[128x208]=26624 | V[128x208]=26624 = 66560
#define AKO 13312
#define AVO (13312 + 26624)
#define ATTN_SMEM_B (13312 + 2 * 26624)
__global__ void __launch_bounds__(256, 2)
attn_k() {
    extern __shared__ char smA[];
    uint32_t sb = smem_u32(smA);

    int tid = threadIdx.x, lane = tid & 31, warp = tid >> 5;
    int gid = lane >> 2, tig = lane & 3;
    int wq = warp & 3, kh = warp >> 2;     // row-group, key-half
    int wm = wq * 16;
    int qb = blockIdx.x;                   // q row block (0..7), 64 rows
    int tbh = blockIdx.y;                  // (t*B+b)*H + h
    int h = tbh & 7, tb = tbh >> 3;
    int kvh = h >> 2;
    int qcol = h * HD_;
    int kcol = D_ + kvh * HD_;
    int vcol = D_ + MKV_ + kvh * HD_;
    int rowbase = tb * C_;

    uint32_t q_base = sb + (wm + (lane & 15)) * 208 + (lane >> 4) * 16;
    uint32_t k_base = sb + AKO + (kh * 64 + ((lane >> 4) << 3) + (lane & 7)) * 208
                      + ((lane >> 3) & 1) * 16;
    uint32_t v_base = sb + AVO + (kh * 64 + (lane & 15)) * 208 + (lane >> 4) * 16;

    // Q tile: 64 rows x 96 cols = 768 16B chunks
#pragma unroll
    for (int it = 0; it < 3; it++) {
        int idx = tid + it * 256;
        int r = idx / 12, c = idx % 12;
        cpa16(sb + r * 208 + c * 16,
              (const char*)(g_sp + (size_t)(rowbase + qb * 64 + r) * NCAT_ + qcol) + c * 16);
    }

    float acc2[12][4];          // partial over this warp's key half
#pragma unroll
    for (int b = 0; b < 12; b++)
#pragma unroll
        for (int c = 0; c < 4; c++) acc2[b][c] = 0.f;

    for (int kc = 0; kc < 4; kc++) {
        // load K,V chunk (128 keys x 96 each)
#pragma unroll
        for (int it = 0; it < 6; it++) {
            int idx = tid + it * 256;
            int r = idx / 12, c = idx % 12;
            cpa16(sb + AKO + r * 208 + c * 16,
                  (const char*)(g_sp + (size_t)(rowbase + kc * 128 + r) * NCAT_ + kcol) + c * 16);
        }
#pragma unroll
        for (int it = 0; it < 6; it++) {
            int idx = tid + it * 256;
            int r = idx / 12, c = idx % 12;
            cpa16(sb + AVO + r * 208 + c * 16,
                  (const char*)(g_sp + (size_t)(rowbase + kc * 128 + r) * NCAT_ + vcol) + c * 16);
        }
        CP_COMMIT();
        CP_WAIT(0);
        __syncthreads();

        // mma1: counts = q @ k^T  (16 rows x 64 keys, K=96) — exact integers
        float acc1[8][4];
#pragma unroll
        for (int b = 0; b < 8; b++)
#pragma unroll
            for (int c = 0; c < 4; c++) acc1[b][c] = 0.f;
#pragma unroll
        for (int kk = 0; kk < 6; kk++) {
            uint32_t aq[4];
            ldsm_x4(aq, q_base + kk * 32);
#pragma unroll
            for (int j = 0; j < 4; j++) {
                uint32_t bk[4];
                ldsm_x4(bk, k_base + j * (16 * 208) + kk * 32);
                mma_bf16(acc1[2 * j], aq, bk);
                mma_bf16(acc1[2 * j + 1], aq, bk + 2);
            }
        }

        // mma2: acc2 += counts @ v  (16 x 96, K=64) — P in registers
#pragma unroll
        for (int kk = 0; kk < 4; kk++) {
            uint32_t af[4];
            af[0] = pack_bf16x2(acc1[2 * kk][0], acc1[2 * kk][1]);
            af[1] = pack_bf16x2(acc1[2 * kk][2], acc1[2 * kk][3]);
            af[2] = pack_bf16x2(acc1[2 * kk + 1][0], acc1[2 * kk + 1][1]);
            af[3] = pack_bf16x2(acc1[2 * kk + 1][2], acc1[2 * kk + 1][3]);
#pragma unroll
            for (int g = 0; g < 6; g++) {
                uint32_t bv[4];
                ldsm_x4_t(bv, v_base + kk * (16 * 208) + g * 32);
                mma_bf16(acc2[2 * g], af, bv);
                mma_bf16(acc2[2 * g + 1], af, bv + 2);
            }
        }
        __syncthreads();
    }

    // cross-half reduction: kh=1 warps dump acc2 into (dead) K buffer
    float* scr = (float*)(smA + AKO);
    int sbase_i = (wq * 32 + lane) * 48;
    if (kh == 1) {
#pragma unroll
        for (int nt = 0; nt < 12; nt++)
#pragma unroll
            for (int c = 0; c < 4; c++) scr[sbase_i + nt * 4 + c] = acc2[nt][c];
    }
    __syncthreads();
    if (kh == 0) {
#pragma unroll
        for (int nt = 0; nt < 12; nt++)
#pragma unroll
            for (int c = 0; c < 4; c++) acc2[nt][c] += scr[sbase_i + nt * 4 + c];

        // epilogue: scale by 0.1, hi/lo split for the wo GEMM
#pragma unroll
        for (int nt = 0; nt < 12; nt++) {
            int r = rowbase + qb * 64 + wm + gid;
            int cb = qcol + nt * 8 + tig * 2;
#pragma unroll
            for (int half = 0; half < 2; half++) {
                int rr = r + half * 8;
                float v0 = 0.1f * acc2[nt][half * 2 + 0];
                float v1 = 0.1f * acc2[nt][half * 2 + 1];
                __nv_bfloat162 hi2, lo2;
                hi2.x = __float2bfloat16(v0);
                hi2.y = __float2bfloat16(v1);
                lo2.x = __float2bfloat16(v0 - __bfloat162float(hi2.x));
                lo2.y = __float2bfloat16(v1 - __bfloat162float(hi2.y));
                *(__nv_bfloat162*)(g_ahi + (size_t)rr * D_ + cb) = hi2;
                *(__nv_bfloat162*)(g_alo + (size_t)rr * D_ + cb) = lo2;
            }
        }
    }
}

// ---------------- kernel 5: output GEMM  d_out = attn @ wo^T ----------------
// r8 (WIN): cp.async.ca double buffer; A/B hi/lo -> 3 MMAs per k-step.
#define WSTGB (4 * PTILEB)     // 40960
__global__ void __launch_bounds__(256)
gemm_wo_k(float* __restrict__ out) {
    extern __shared__ __nv_bfloat16 smw[];
    uint32_t sbase = smem_u32(smw);
    int tid = threadIdx.x;
    int lane = tid & 31, warp = tid >> 5;
    int gid = lane >> 2, tig = lane & 3;
    int wm = (warp >> 2) * 64, wn = (warp & 3) * 32;
    int m0 = blockIdx.y * 128, n0 = blockIdx.x * 128;

    uint32_t a_off = (wm + (lane & 15)) * PSTRB + (lane >> 4) * 16;
    uint32_t b_off = (wn + ((lane >> 4) << 3) + (lane & 7)) * PSTRB + ((lane >> 3) & 1) * 16;

    float acc[4][4][4];
#pragma unroll
    for (int a = 0; a < 4; a++)
#pragma unroll
        for (int b = 0; b < 4; b++)
#pragma unroll
            for (int c = 0; c < 4; c++) acc[a][b][c] = 0.f;

    int r0 = tid >> 2, c4b = (tid & 3) * 16;

#pragma unroll
    for (int it = 0; it < 2; it++) {
        int rr = r0 + it * 64;
        cpa16(sbase + rr * PSTRB + c4b,
              (const char*)(g_ahi + (size_t)(m0 + rr) * D_) + c4b);
        cpa16(sbase + PTILEB + rr * PSTRB + c4b,
              (const char*)(g_alo + (size_t)(m0 + rr) * D_) + c4b);
        cpa16(sbase + 2 * PTILEB + rr * PSTRB + c4b,
              (const char*)(g_WOhi + (size_t)(n0 + rr) * D_) + c4b);
        cpa16(sbase + 3 * PTILEB + rr * PSTRB + c4b,
              (const char*)(g_WOlo + (size_t)(n0 + rr) * D_) + c4b);
    }
    CP_COMMIT();

    for (int c = 0; c < NCH; c++) {
        if (c + 1 < NCH) {
            uint32_t st = ((c + 1) & 1) * WSTGB;
            int kb = (c + 1) * 64;
#pragma unroll
            for (int it = 0; it < 2; it++) {
                int rr = r0 + it * 64;
                cpa16(sbase + st + rr * PSTRB + c4b,
                      (const char*)(g_ahi + (size_t)(m0 + rr) * D_) + kb + c4b);
                cpa16(sbase + st + PTILEB + rr * PSTRB + c4b,
                      (const char*)(g_alo + (size_t)(m0 + rr) * D_) + kb + c4b);
                cpa16(sbase + st + 2 * PTILEB + rr * PSTRB + c4b,
                      (const char*)(g_WOhi + (size_t)(n0 + rr) * D_) + kb + c4b);
                cpa16(sbase + st + 3 * PTILEB + rr * PSTRB + c4b,
                      (const char*)(g_WOlo + (size_t)(n0 + rr) * D_) + kb + c4b);
            }
            CP_COMMIT();
            CP_WAIT(1);
        } else {
            CP_WAIT(0);
        }
        __syncthreads();
        uint32_t off = (c & 1) * WSTGB;
        uint32_t ah_base = sbase + off + a_off;
        uint32_t al_base = sbase + off + PTILEB + a_off;
        uint32_t bh_base = sbase + off + 2 * PTILEB + b_off;
        uint32_t bl_base = sbase + off + 3 * PTILEB + b_off;
#pragma unroll
        for (int kk = 0; kk < 2; kk++) {
            uint32_t afh[4][4], afl[4][4], bh[2][4], bl[2][4];
#pragma unroll
            for (int mt = 0; mt < 4; mt++) {
                ldsm_x4(afh[mt], ah_base + mt * (16 * PSTRB) + kk * 32);
                ldsm_x4(afl[mt], al_base + mt * (16 * PSTRB) + kk * 32);
            }
#pragma unroll
            for (int j = 0; j < 2; j++) {
                ldsm_x4(bh[j], bh_base + j * (16 * PSTRB) + kk * 32);
                ldsm_x4(bl[j], bl_base + j * (16 * PSTRB) + kk * 32);
            }
#pragma unroll
            for (int nt = 0; nt < 4; nt++) {
                const uint32_t* bhp = &bh[nt >> 1][(nt & 1) * 2];
                const uint32_t* blp = &bl[nt >> 1][(nt & 1) * 2];
#pragma unroll
                for (int mt = 0; mt < 4; mt++) {
                    mma_bf16(acc[mt][nt], afh[mt], bhp);
                    mma_bf16(acc[mt][nt], afh[mt], blp);
                    mma_bf16(acc[mt][nt], afl[mt], bhp);
                }
            }
        }
        __syncthreads();
    }
#pragma unroll
    for (int mt = 0; mt < 4; mt++)
#pragma unroll
        for (int nt = 0; nt < 4; nt++) {
            int r = m0 + wm + mt * 16 + gid;
            int c = n0 + wn + nt * 8 + tig * 2;
            *(float2*)(out + (size_t)r * D_ + c) = make_float2(acc[mt][nt][0], acc[mt][nt][1]);
            *(float2*)(out + (size_t)(r + 8) * D_ + c) = make_float2(acc[mt][nt][2], acc[mt][nt][3]);
        }
}

// ---------------- launch ----------------
extern "C" void kernel_launch(void* const* d_in, const int* in_sizes, int n_in,
                              void* d_out, int out_size) {
    (void)in_sizes; (void)n_in; (void)out_size;
    const float* x   = (const float*)d_in[0];
    const float* qw  = (const float*)d_in[1];
    const float* kw  = (const float*)d_in[2];
    const float* vw  = (const float*)d_in[3];
    const float* wow = (const float*)d_in[4];
    float* out = (float*)d_out;

    const int PROJ_SMEM = 2 * PSTGB;   // 61440
    const int WO_SMEM   = 2 * WSTGB;   // 81920
    cudaFuncSetAttribute(attn_k, cudaFuncAttributeMaxDynamicSharedMemorySize, ATTN_SMEM_B);
    cudaFuncSetAttribute(gemm_proj_fused, cudaFuncAttributeMaxDynamicSharedMemorySize, PROJ_SMEM);
    cudaFuncSetAttribute(gemm_wo_k, cudaFuncAttributeMaxDynamicSharedMemorySize, WO_SMEM);

    pack_w_k<<<(NCAT_ * D_ + 255) / 256, 256>>>(qw, kw, vw, wow);
    lif_x_k<<<(BCD_ + 255) / 256, 256>>>(x);
    gemm_proj_fused<<<dim3(NCAT_ / 128, BC_ / 128), 256, PROJ_SMEM>>>();
    attn_k<<<dim3(C_ / 64, T_ * B_ * H_), 256, ATTN_SMEM_B>>>();
    gemm_wo_k<<<dim3(D_ / 128, M_ / 128), 256, WO_SMEM>>>(out);
}

// round 16
// speedup vs baseline: 1.0262x; 1.0262x over previous
#include <cuda_runtime.h>
#include <cuda_bf16.h>
#include <cstdint>

#define T_ 4
#define B_ 8
#define C_ 512
#define D_ 768
#define H_ 8
#define HD_ 96
#define MKV_ 192
#define NCAT_ 1152            // 768 (q) + 192 (k) + 192 (v)
#define BC_ 4096              // B*C
#define M_ 16384              // T*B*C
#define BCD_ 3145728          // B*C*D

// ---------------- scratch (device globals: no allocation allowed) ----------
__device__ __nv_bfloat16 g_xs[M_ * D_];        // proj_lif spikes (exact 0/1)
__device__ __nv_bfloat16 g_Whi[NCAT_ * D_];    // concat [q_w; k_w; v_w] hi
__device__ __nv_bfloat16 g_Wlo[NCAT_ * D_];    // lo residual
__device__ __nv_bfloat16 g_WOhi[D_ * D_];
__device__ __nv_bfloat16 g_WOlo[D_ * D_];
__device__ __nv_bfloat16 g_sp[M_ * NCAT_];     // q/k/v spikes (bf16 0/1, exact)
__device__ __nv_bfloat16 g_ahi[M_ * D_];       // attention output hi
__device__ __nv_bfloat16 g_alo[M_ * D_];       // attention output lo

// ---------------- helpers ----------------
__device__ __forceinline__ uint32_t smem_u32(const void* p) {
    uint32_t a;
    asm("{ .reg .u64 t; cvta.to.shared.u64 t, %1; cvt.u32.u64 %0, t; }" : "=r"(a) : "l"(p));
    return a;
}
__device__ __forceinline__ void mma_bf16(float* c, const uint32_t* a, const uint32_t* b) {
    asm volatile(
        "mma.sync.aligned.m16n8k16.row.col.f32.bf16.bf16.f32 "
        "{%0,%1,%2,%3},{%4,%5,%6,%7},{%8,%9},{%0,%1,%2,%3};\n"
        : "+f"(c[0]), "+f"(c[1]), "+f"(c[2]), "+f"(c[3])
        : "r"(a[0]), "r"(a[1]), "r"(a[2]), "r"(a[3]), "r"(b[0]), "r"(b[1]));
}
__device__ __forceinline__ void ldsm_x4(uint32_t* r, uint32_t addr) {
    asm volatile("ldmatrix.sync.aligned.m8n8.x4.shared.b16 {%0,%1,%2,%3}, [%4];"
        : "=r"(r[0]), "=r"(r[1]), "=r"(r[2]), "=r"(r[3]) : "r"(addr));
}
__device__ __forceinline__ void ldsm_x4_t(uint32_t* r, uint32_t addr) {
    asm volatile("ldmatrix.sync.aligned.m8n8.x4.trans.shared.b16 {%0,%1,%2,%3}, [%4];"
        : "=r"(r[0]), "=r"(r[1]), "=r"(r[2]), "=r"(r[3]) : "r"(addr));
}
__device__ __forceinline__ uint32_t pack_bf16x2(float lo, float hi) {
    uint32_t r;
    asm("cvt.rn.bf16x2.f32 %0, %1, %2;" : "=r"(r) : "f"(hi), "f"(lo));
    return r;
}
__device__ __forceinline__ void cpa16(uint32_t dst, const void* src) {
    asm volatile("cp.async.ca.shared.global [%0], [%1], 16;" :: "r"(dst), "l"(src));
}
#define CP_COMMIT()  asm volatile("cp.async.commit_group;" ::: "memory")
#define CP_WAIT(n)   asm volatile("cp.async.wait_group %0;" :: "n"(n) : "memory")

// ---------------- kernel 1: split weights into bf16 hi/lo ----------------
__global__ void pack_w_k(const float* __restrict__ qw, const float* __restrict__ kw,
                         const float* __restrict__ vw, const float* __restrict__ wow) {
    int i = blockIdx.x * 256 + threadIdx.x;
    if (i < NCAT_ * D_) {
        int n = i / D_, k = i - n * D_;
        float w;
        if (n < D_)            w = qw[i];
        else if (n < D_ + MKV_) w = kw[(n - D_) * D_ + k];
        else                    w = vw[(n - D_ - MKV_) * D_ + k];
        __nv_bfloat16 hi = __float2bfloat16(w);
        g_Whi[i] = hi;
        g_Wlo[i] = __float2bfloat16(w - __bfloat162float(hi));
    }
    if (i < D_ * D_) {
        float w = wow[i];
        __nv_bfloat16 hi = __float2bfloat16(w);
        g_WOhi[i] = hi;
        g_WOlo[i] = __float2bfloat16(w - __bfloat162float(hi));
    }
}

// ---------------- kernel 2: LIF on x -> xs spikes (bf16 exact) -------------
__global__ void lif_x_k(const float* __restrict__ x) {
    int i = blockIdx.x * 256 + threadIdx.x;
    if (i >= BCD_) return;
    float v = 0.f;
#pragma unroll
    for (int t = 0; t < T_; t++) {
        v = v * 0.5f + x[t * BCD_ + i];
        bool s = (v >= 1.0f);
        g_xs[t * BCD_ + i] = __float2bfloat16(s ? 1.f : 0.f);
        if (s) v = 0.f;
    }
}

// ====== kernel 3: FUSED projection GEMM + LIF (membrane-in-accumulator) ====
#define PSTR 40                 // smem row stride, bf16 units
#define PSTRB 80                // ... bytes
#define PTILE (128 * PSTR)      // tile bf16 units
#define PTILEB (128 * PSTRB)    // tile bytes (10240)
#define PSTGB (3 * PTILEB)      // 30720
#define NCH 24                  // K=768 / 32
__global__ void __launch_bounds__(256, 2)
gemm_proj_fused() {
    extern __shared__ __nv_bfloat16 smp[];
    uint32_t sbase = smem_u32(smp);
    int tid = threadIdx.x;
    int lane = tid & 31, warp = tid >> 5;
    int gid = lane >> 2, tig = lane & 3;
    int wm = (warp >> 2) * 64, wn = (warp & 3) * 32;
    int m0 = blockIdx.y * 128;            // within one t-slice (BC rows)
    int n0 = blockIdx.x * 128;

    uint32_t a_off = (wm + (lane & 15)) * PSTRB + (lane >> 4) * 16;
    uint32_t b_off = (wn + ((lane >> 4) << 3) + (lane & 7)) * PSTRB + ((lane >> 3) & 1) * 16;

    float acc[4][4][4];                   // doubles as LIF membrane (x0.5)
#pragma unroll
    for (int a = 0; a < 4; a++)
#pragma unroll
        for (int b = 0; b < 4; b++)
#pragma unroll
            for (int c = 0; c < 4; c++) acc[a][b][c] = 0.f;

    int r0 = tid >> 2, c4b = (tid & 3) * 16;

    for (int t = 0; t < T_; t++) {
        size_t mrow = (size_t)(t * BC_ + m0);
#pragma unroll
        for (int it = 0; it < 2; it++) {
            int rr = r0 + it * 64;
            cpa16(sbase + rr * PSTRB + c4b,
                  (const char*)(g_xs + (mrow + rr) * D_) + c4b);
            cpa16(sbase + PTILEB + rr * PSTRB + c4b,
                  (const char*)(g_Whi + (size_t)(n0 + rr) * D_) + c4b);
            cpa16(sbase + 2 * PTILEB + rr * PSTRB + c4b,
                  (const char*)(g_Wlo + (size_t)(n0 + rr) * D_) + c4b);
        }
        CP_COMMIT();

        for (int c = 0; c < NCH; c++) {
            if (c + 1 < NCH) {
                uint32_t st = ((c + 1) & 1) * PSTGB;
                int kb = (c + 1) * 64;
#pragma unroll
                for (int it = 0; it < 2; it++) {
                    int rr = r0 + it * 64;
                    cpa16(sbase + st + rr * PSTRB + c4b,
                          (const char*)(g_xs + (mrow + rr) * D_) + kb + c4b);
                    cpa16(sbase + st + PTILEB + rr * PSTRB + c4b,
                          (const char*)(g_Whi + (size_t)(n0 + rr) * D_) + kb + c4b);
                    cpa16(sbase + st + 2 * PTILEB + rr * PSTRB + c4b,
                          (const char*)(g_Wlo + (size_t)(n0 + rr) * D_) + kb + c4b);
                }
                CP_COMMIT();
                CP_WAIT(1);
            } else {
                CP_WAIT(0);
            }
            __syncthreads();
            uint32_t off = (c & 1) * PSTGB;
            uint32_t a_base = sbase + off + a_off;
            uint32_t bh_base = sbase + off + PTILEB + b_off;
            uint32_t bl_base = sbase + off + 2 * PTILEB + b_off;
#pragma unroll
            for (int kk = 0; kk < 2; kk++) {
                uint32_t af[4][4], bh[2][4], bl[2][4];
#pragma unroll
                for (int mt = 0; mt < 4; mt++)
                    ldsm_x4(af[mt], a_base + mt * (16 * PSTRB) + kk * 32);
#pragma unroll
                for (int j = 0; j < 2; j++) {
                    ldsm_x4(bh[j], bh_base + j * (16 * PSTRB) + kk * 32);
                    ldsm_x4(bl[j], bl_base + j * (16 * PSTRB) + kk * 32);
                }
#pragma unroll
                for (int nt = 0; nt < 4; nt++) {
                    const uint32_t* bhp = &bh[nt >> 1][(nt & 1) * 2];
                    const uint32_t* blp = &bl[nt >> 1][(nt & 1) * 2];
#pragma unroll
                    for (int mt = 0; mt < 4; mt++) {
                        mma_bf16(acc[mt][nt], af[mt], bhp);
                        mma_bf16(acc[mt][nt], af[mt], blp);
                    }
                }
            }
            __syncthreads();
        }

        // LIF epilogue for this t: acc == v_t. Emit spikes, set acc = 0.5*v'.
#pragma unroll
        for (int mt = 0; mt < 4; mt++)
#pragma unroll
            for (int nt = 0; nt < 4; nt++) {
                int col = n0 + wn + nt * 8 + tig * 2;
                uint32_t w[2];
#pragma unroll
                for (int half = 0; half < 2; half++) {
                    uint32_t pk = 0;
#pragma unroll
                    for (int j = 0; j < 2; j++) {
                        int i = half * 2 + j;
                        float v = acc[mt][nt][i];
                        bool sp = (v >= 1.0f);
                        if (sp) pk |= 0x3F80u << (j * 16);
                        acc[mt][nt][i] = sp ? 0.f : v * 0.5f;
                    }
                    w[half] = pk;
                }
                size_t r = mrow + wm + mt * 16 + gid;
                *(uint32_t*)(g_sp + r * NCAT_ + col) = w[0];
                *(uint32_t*)(g_sp + (r + 8) * NCAT_ + col) = w[1];
            }
    }
}

// ====== kernel 4: attention, register-resident P + hoisted Q fragments =====
// r14 structure (measured best); Q ldsm hoisted out of the kc loop.
// smem bytes: Q[128x208]=26624 | K0,K1[128x208] | V0,V1[128x208] = 133120
#define AOK0 26624
#define AOV0 (26624 * 3)
#define ATTN_SMEM_B (26624 * 5)
__global__ void __launch_bounds__(256)
attn_k() {
    extern __shared__ char smA[];
    uint32_t sb = smem_u32(smA);

    int tid = threadIdx.x, lane = tid & 31, warp = tid >> 5;
    int gid = lane >> 2, tig = lane & 3;
    int wm = warp * 16;         // 8 warps x 16 q-rows
    int qb = blockIdx.x;        // q row block (0..3)
    int tbh = blockIdx.y;       // (t*B+b)*H + h
    int h = tbh & 7, tb = tbh >> 3;
    int kvh = h >> 2;
    int qcol = h * HD_;
    int kcol = D_ + kvh * HD_;
    int vcol = D_ + MKV_ + kvh * HD_;
    int rowbase = tb * C_;

    uint32_t q_base = sb + (wm + (lane & 15)) * 208 + (lane >> 4) * 16;
    uint32_t k_off = (((lane >> 4) << 3) + (lane & 7)) * 208 + ((lane >> 3) & 1) * 16;
    uint32_t v_off = (lane & 15) * 208 + (lane >> 4) * 16;   // trans-ldsm
    uint32_t k_stage[2] = { sb + AOK0 + k_off, sb + AOK0 + 26624 + k_off };
    uint32_t v_stage[2] = { sb + AOV0 + v_off, sb + AOV0 + 26624 + v_off };

    // prologue: Q + K(kc=0) + V(kc=0), one commit group
#pragma unroll
    for (int it = 0; it < 6; it++) {
        int idx = tid + it * 256;
        int r = idx / 12, c = idx % 12;
        cpa16(sb + r * 208 + c * 16,
              (const char*)(g_sp + (size_t)(rowbase + qb * 128 + r) * NCAT_ + qcol) + c * 16);
    }
#pragma unroll
    for (int it = 0; it < 6; it++) {
        int idx = tid + it * 256;
        int r = idx / 12, c = idx % 12;
        cpa16(sb + AOK0 + r * 208 + c * 16,
              (const char*)(g_sp + (size_t)(rowbase + r) * NCAT_ + kcol) + c * 16);
    }
#pragma unroll
    for (int it = 0; it < 6; it++) {
        int idx = tid + it * 256;
        int r = idx / 12, c = idx % 12;
        cpa16(sb + AOV0 + r * 208 + c * 16,
              (const char*)(g_sp + (size_t)(rowbase + r) * NCAT_ + vcol) + c * 16);
    }
    CP_COMMIT();

    float acc2[12][4];          // 96 d-cols, 12 n-tiles
#pragma unroll
    for (int b = 0; b < 12; b++)
#pragma unroll
        for (int c = 0; c < 4; c++) acc2[b][c] = 0.f;

    uint32_t aq[6][4];          // hoisted Q fragments (loaded once, kc 0)
    bool qloaded = false;

    for (int kc = 0; kc < 4; kc++) {
        if (kc + 1 < 4) {
            uint32_t kst = sb + AOK0 + ((kc + 1) & 1) * 26624;
            uint32_t vst = sb + AOV0 + ((kc + 1) & 1) * 26624;
#pragma unroll
            for (int it = 0; it < 6; it++) {
                int idx = tid + it * 256;
                int r = idx / 12, c = idx % 12;
                cpa16(kst + r * 208 + c * 16,
                      (const char*)(g_sp + (size_t)(rowbase + (kc + 1) * 128 + r) * NCAT_ + kcol) + c * 16);
            }
#pragma unroll
            for (int it = 0; it < 6; it++) {
                int idx = tid + it * 256;
                int r = idx / 12, c = idx % 12;
                cpa16(vst + r * 208 + c * 16,
                      (const char*)(g_sp + (size_t)(rowbase + (kc + 1) * 128 + r) * NCAT_ + vcol) + c * 16);
            }
            CP_COMMIT();
            CP_WAIT(1);
        } else {
            CP_WAIT(0);
        }
        __syncthreads();
        int st = kc & 1;

        if (!qloaded) {
#pragma unroll
            for (int kk = 0; kk < 6; kk++) ldsm_x4(aq[kk], q_base + kk * 32);
            qloaded = true;
        }

        // mma1: counts = q @ k^T  (16 rows x 128 keys, K=96) — exact integers
        float acc1[16][4];
#pragma unroll
        for (int b = 0; b < 16; b++)
#pragma unroll
            for (int c = 0; c < 4; c++) acc1[b][c] = 0.f;
#pragma unroll
        for (int kk = 0; kk < 6; kk++) {
#pragma unroll
            for (int j = 0; j < 8; j++) {
                uint32_t bk[4];
                ldsm_x4(bk, k_stage[st] + j * (16 * 208) + kk * 32);
                mma_bf16(acc1[2 * j], aq[kk], bk);
                mma_bf16(acc1[2 * j + 1], aq[kk], bk + 2);
            }
        }

        // mma2: acc2 += counts @ v  (16 x 96, K=128) — P stays in registers
#pragma unroll
        for (int kk = 0; kk < 8; kk++) {
            uint32_t af[4];
            af[0] = pack_bf16x2(acc1[2 * kk][0], acc1[2 * kk][1]);
            af[1] = pack_bf16x2(acc1[2 * kk][2], acc1[2 * kk][3]);
            af[2] = pack_bf16x2(acc1[2 * kk + 1][0], acc1[2 * kk + 1][1]);
            af[3] = pack_bf16x2(acc1[2 * kk + 1][2], acc1[2 * kk + 1][3]);
#pragma unroll
            for (int g = 0; g < 6; g++) {
                uint32_t bv[4];
                ldsm_x4_t(bv, v_stage[st] + kk * (16 * 208) + g * 32);
                mma_bf16(acc2[2 * g], af, bv);
                mma_bf16(acc2[2 * g + 1], af, bv + 2);
            }
        }
        __syncthreads();
    }

    // epilogue: scale by 0.1, hi/lo split for the wo GEMM
#pragma unroll
    for (int nt = 0; nt < 12; nt++) {
        int r = rowbase + qb * 128 + wm + gid;
        int cb = qcol + nt * 8 + tig * 2;
#pragma unroll
        for (int half = 0; half < 2; half++) {
            int rr = r + half * 8;
            float v0 = 0.1f * acc2[nt][half * 2 + 0];
            float v1 = 0.1f * acc2[nt][half * 2 + 1];
            __nv_bfloat162 hi2, lo2;
            hi2.x = __float2bfloat16(v0);
            hi2.y = __float2bfloat16(v1);
            lo2.x = __float2bfloat16(v0 - __bfloat162float(hi2.x));
            lo2.y = __float2bfloat16(v1 - __bfloat162float(hi2.y));
            *(__nv_bfloat162*)(g_ahi + (size_t)rr * D_ + cb) = hi2;
            *(__nv_bfloat162*)(g_alo + (size_t)rr * D_ + cb) = lo2;
        }
    }
}

// ---------------- kernel 5: output GEMM  d_out = attn @ wo^T ----------------
// r8 (WIN): cp.async.ca double buffer; A/B hi/lo -> 3 MMAs per k-step.
#define WSTGB (4 * PTILEB)     // 40960
__global__ void __launch_bounds__(256)
gemm_wo_k(float* __restrict__ out) {
    extern __shared__ __nv_bfloat16 smw[];
    uint32_t sbase = smem_u32(smw);
    int tid = threadIdx.x;
    int lane = tid & 31, warp = tid >> 5;
    int gid = lane >> 2, tig = lane & 3;
    int wm = (warp >> 2) * 64, wn = (warp & 3) * 32;
    int m0 = blockIdx.y * 128, n0 = blockIdx.x * 128;

    uint32_t a_off = (wm + (lane & 15)) * PSTRB + (lane >> 4) * 16;
    uint32_t b_off = (wn + ((lane >> 4) << 3) + (lane & 7)) * PSTRB + ((lane >> 3) & 1) * 16;

    float acc[4][4][4];
#pragma unroll
    for (int a = 0; a < 4; a++)
#pragma unroll
        for (int b = 0; b < 4; b++)
#pragma unroll
            for (int c = 0; c < 4; c++) acc[a][b][c] = 0.f;

    int r0 = tid >> 2, c4b = (tid & 3) * 16;

#pragma unroll
    for (int it = 0; it < 2; it++) {
        int rr = r0 + it * 64;
        cpa16(sbase + rr * PSTRB + c4b,
              (const char*)(g_ahi + (size_t)(m0 + rr) * D_) + c4b);
        cpa16(sbase + PTILEB + rr * PSTRB + c4b,
              (const char*)(g_alo + (size_t)(m0 + rr) * D_) + c4b);
        cpa16(sbase + 2 * PTILEB + rr * PSTRB + c4b,
              (const char*)(g_WOhi + (size_t)(n0 + rr) * D_) + c4b);
        cpa16(sbase + 3 * PTILEB + rr * PSTRB + c4b,
              (const char*)(g_WOlo + (size_t)(n0 + rr) * D_) + c4b);
    }
    CP_COMMIT();

    for (int c = 0; c < NCH; c++) {
        if (c + 1 < NCH) {
            uint32_t st = ((c + 1) & 1) * WSTGB;
            int kb = (c + 1) * 64;
#pragma unroll
            for (int it = 0; it < 2; it++) {
                int rr = r0 + it * 64;
                cpa16(sbase + st + rr * PSTRB + c4b,
                      (const char*)(g_ahi + (size_t)(m0 + rr) * D_) + kb + c4b);
                cpa16(sbase + st + PTILEB + rr * PSTRB + c4b,
                      (const char*)(g_alo + (size_t)(m0 + rr) * D_) + kb + c4b);
                cpa16(sbase + st + 2 * PTILEB + rr * PSTRB + c4b,
                      (const char*)(g_WOhi + (size_t)(n0 + rr) * D_) + kb + c4b);
                cpa16(sbase + st + 3 * PTILEB + rr * PSTRB + c4b,
                      (const char*)(g_WOlo + (size_t)(n0 + rr) * D_) + kb + c4b);
            }
            CP_COMMIT();
            CP_WAIT(1);
        } else {
            CP_WAIT(0);
        }
        __syncthreads();
        uint32_t off = (c & 1) * WSTGB;
        uint32_t ah_base = sbase + off + a_off;
        uint32_t al_base = sbase + off + PTILEB + a_off;
        uint32_t bh_base = sbase + off + 2 * PTILEB + b_off;
        uint32_t bl_base = sbase + off + 3 * PTILEB + b_off;
#pragma unroll
        for (int kk = 0; kk < 2; kk++) {
            uint32_t afh[4][4], afl[4][4], bh[2][4], bl[2][4];
#pragma unroll
            for (int mt = 0; mt < 4; mt++) {
                ldsm_x4(afh[mt], ah_base + mt * (16 * PSTRB) + kk * 32);
                ldsm_x4(afl[mt], al_base + mt * (16 * PSTRB) + kk * 32);
            }
#pragma unroll
            for (int j = 0; j < 2; j++) {
                ldsm_x4(bh[j], bh_base + j * (16 * PSTRB) + kk * 32);
                ldsm_x4(bl[j], bl_base + j * (16 * PSTRB) + kk * 32);
            }
#pragma unroll
            for (int nt = 0; nt < 4; nt++) {
                const uint32_t* bhp = &bh[nt >> 1][(nt & 1) * 2];
                const uint32_t* blp = &bl[nt >> 1][(nt & 1) * 2];
#pragma unroll
                for (int mt = 0; mt < 4; mt++) {
                    mma_bf16(acc[mt][nt], afh[mt], bhp);
                    mma_bf16(acc[mt][nt], afh[mt], blp);
                    mma_bf16(acc[mt][nt], afl[mt], bhp);
                }
            }
        }
        __syncthreads();
    }
#pragma unroll
    for (int mt = 0; mt < 4; mt++)
#pragma unroll
        for (int nt = 0; nt < 4; nt++) {
            int r = m0 + wm + mt * 16 + gid;
            int c = n0 + wn + nt * 8 + tig * 2;
            *(float2*)(out + (size_t)r * D_ + c) = make_float2(acc[mt][nt][0], acc[mt][nt][1]);
            *(float2*)(out + (size_t)(r + 8) * D_ + c) = make_float2(acc[mt][nt][2], acc[mt][nt][3]);
        }
}

// ---------------- launch ----------------
extern "C" void kernel_launch(void* const* d_in, const int* in_sizes, int n_in,
                              void* d_out, int out_size) {
    (void)in_sizes; (void)n_in; (void)out_size;
    const float* x   = (const float*)d_in[0];
    const float* qw  = (const float*)d_in[1];
    const float* kw  = (const float*)d_in[2];
    const float* vw  = (const float*)d_in[3];
    const float* wow = (const float*)d_in[4];
    float* out = (float*)d_out;

    const int PROJ_SMEM = 2 * PSTGB;   // 61440
    const int WO_SMEM   = 2 * WSTGB;   // 81920
    cudaFuncSetAttribute(attn_k, cudaFuncAttributeMaxDynamicSharedMemorySize, ATTN_SMEM_B);
    cudaFuncSetAttribute(gemm_proj_fused, cudaFuncAttributeMaxDynamicSharedMemorySize, PROJ_SMEM);
    cudaFuncSetAttribute(gemm_wo_k, cudaFuncAttributeMaxDynamicSharedMemorySize, WO_SMEM);

    pack_w_k<<<(NCAT_ * D_ + 255) / 256, 256>>>(qw, kw, vw, wow);
    lif_x_k<<<(BCD_ + 255) / 256, 256>>>(x);
    gemm_proj_fused<<<dim3(NCAT_ / 128, BC_ / 128), 256, PROJ_SMEM>>>();
    attn_k<<<dim3(C_ / 128, T_ * B_ * H_), 256, ATTN_SMEM_B>>>();
    gemm_wo_k<<<dim3(D_ / 128, M_ / 128), 256, WO_SMEM>>>(out);
}